// round 3
// baseline (speedup 1.0000x reference)
#include <cuda_runtime.h>
#include <cstdint>

#define Nn 50000
#define Ee 800000
#define Dd 128
#define Hh 256
#define Tt 10000
#define EPSV 1e-5f
#define STATS_BLOCKS 200

// ---------------- scratch (static device globals; no allocation) ----------------
__device__ float g_disqrt[Nn];
__device__ int   g_cnt[Nn];
__device__ int   g_off[Nn + 1];
__device__ int   g_cursor[Nn];
__device__ int   g_csrc[Ee];
__device__ float g_cnorm[Ee];
__device__ float g_hw[(size_t)Nn * Hh];   // GEMM output hW
__device__ float g_agg[(size_t)Nn * Hh];  // aggregated
__device__ float g_h[(size_t)Nn * Hh];    // activations
__device__ float g_part[STATS_BLOCKS * 2 * Hh];  // BN partials
__device__ float g_stats[2 * Hh];                // [sum | sumsq]
__device__ float g_gath[(size_t)Tt * Hh]; // gathered train rows

// ---------------- graph preprocessing ----------------
__global__ void k_zero_cnt() {
    int i = blockIdx.x * blockDim.x + threadIdx.x;
    if (i < Nn) g_cnt[i] = 0;
}

__global__ void k_count(const int* __restrict__ row) {
    int e = blockIdx.x * blockDim.x + threadIdx.x;
    if (e < Ee) atomicAdd(&g_cnt[row[e]], 1);
}

__global__ void k_disqrt() {
    int i = blockIdx.x * blockDim.x + threadIdx.x;
    if (i < Nn) g_disqrt[i] = rsqrtf((float)g_cnt[i] + 1.0f);
}

__global__ void k_scan() {  // single block, 1024 threads
    const int C = (Nn + 1023) / 1024;  // 49
    int t = threadIdx.x;
    int start = t * C;
    int end = min(start + C, Nn);
    int s = 0;
    for (int i = start; i < end; i++) s += g_cnt[i];
    __shared__ int sh[1024];
    sh[t] = s;
    __syncthreads();
    for (int off = 1; off < 1024; off <<= 1) {
        int v = (t >= off) ? sh[t - off] : 0;
        __syncthreads();
        sh[t] += v;
        __syncthreads();
    }
    int base = (t == 0) ? 0 : sh[t - 1];
    for (int i = start; i < end; i++) {
        g_off[i] = base;
        g_cursor[i] = base;
        base += g_cnt[i];
    }
    if (t == 1023) g_off[Nn] = sh[1023];
}

__global__ void k_scatter(const int* __restrict__ row,
                          const int* __restrict__ col) {
    int e = blockIdx.x * blockDim.x + threadIdx.x;
    if (e < Ee) {
        int d = row[e];
        int s = col[e];
        int pos = atomicAdd(&g_cursor[d], 1);
        g_csrc[pos] = s;
        g_cnorm[pos] = g_disqrt[d] * g_disqrt[s];
    }
}

// ---------------- SGEMM: C[M x 256] = A[M x K] @ B[K x 256] ----------------
// 128x128 tile, BK=8, 256 threads, 8x8 per thread.
__global__ __launch_bounds__(256, 2) void k_sgemm(const float* __restrict__ A,
                                                  const float* __restrict__ B,
                                                  float* __restrict__ C,
                                                  int M, int K) {
    __shared__ float As[8][128];
    __shared__ float Bs[8][128];

    const int tid = threadIdx.x;
    const int rowBase = blockIdx.y * 128;
    const int colBase = blockIdx.x * 128;

    const int arow = tid >> 1;
    const int acol = (tid & 1) * 4;
    const int brow = tid >> 5;
    const int bcol = (tid & 31) * 4;

    const int ty = tid >> 4;  // 0..15
    const int tx = tid & 15;  // 0..15

    float acc[8][8];
#pragma unroll
    for (int m = 0; m < 8; m++)
#pragma unroll
        for (int n = 0; n < 8; n++) acc[m][n] = 0.0f;

    for (int k0 = 0; k0 < K; k0 += 8) {
        float4 av = make_float4(0.f, 0.f, 0.f, 0.f);
        int grow = rowBase + arow;
        if (grow < M)
            av = *(const float4*)(A + (size_t)grow * K + k0 + acol);
        As[acol + 0][arow] = av.x;
        As[acol + 1][arow] = av.y;
        As[acol + 2][arow] = av.z;
        As[acol + 3][arow] = av.w;
        float4 bv = *(const float4*)(B + (size_t)(k0 + brow) * Hh + colBase + bcol);
        *(float4*)&Bs[brow][bcol] = bv;
        __syncthreads();

#pragma unroll
        for (int kk = 0; kk < 8; kk++) {
            float ar[8], br[8];
            float4 a0 = *(const float4*)&As[kk][ty * 8];
            float4 a1 = *(const float4*)&As[kk][ty * 8 + 4];
            float4 b0 = *(const float4*)&Bs[kk][tx * 8];
            float4 b1 = *(const float4*)&Bs[kk][tx * 8 + 4];
            ar[0] = a0.x; ar[1] = a0.y; ar[2] = a0.z; ar[3] = a0.w;
            ar[4] = a1.x; ar[5] = a1.y; ar[6] = a1.z; ar[7] = a1.w;
            br[0] = b0.x; br[1] = b0.y; br[2] = b0.z; br[3] = b0.w;
            br[4] = b1.x; br[5] = b1.y; br[6] = b1.z; br[7] = b1.w;
#pragma unroll
            for (int m = 0; m < 8; m++)
#pragma unroll
                for (int n = 0; n < 8; n++) acc[m][n] = fmaf(ar[m], br[n], acc[m][n]);
        }
        __syncthreads();
    }

#pragma unroll
    for (int m = 0; m < 8; m++) {
        int grow = rowBase + ty * 8 + m;
        if (grow < M) {
            float* cp = C + (size_t)grow * Hh + colBase + tx * 8;
            *(float4*)cp = make_float4(acc[m][0], acc[m][1], acc[m][2], acc[m][3]);
            *(float4*)(cp + 4) = make_float4(acc[m][4], acc[m][5], acc[m][6], acc[m][7]);
        }
    }
}

// ---------------- aggregation: warp per destination node ----------------
__global__ void k_agg() {
    int warp = (blockIdx.x * blockDim.x + threadIdx.x) >> 5;
    int lane = threadIdx.x & 31;
    if (warp >= Nn) return;
    int i = warp;

    const float4* hw4 = (const float4*)g_hw;
    float dsq = g_disqrt[i];
    float sl = dsq * dsq;  // self-loop norm

    float4 v0 = hw4[(size_t)i * 64 + lane];
    float4 v1 = hw4[(size_t)i * 64 + 32 + lane];
    float4 acc0 = make_float4(v0.x * sl, v0.y * sl, v0.z * sl, v0.w * sl);
    float4 acc1 = make_float4(v1.x * sl, v1.y * sl, v1.z * sl, v1.w * sl);

    int e0 = g_off[i];
    int e1 = g_off[i + 1];
    for (int e = e0; e < e1; e++) {
        int s = g_csrc[e];
        float nm = g_cnorm[e];
        float4 w0 = hw4[(size_t)s * 64 + lane];
        float4 w1 = hw4[(size_t)s * 64 + 32 + lane];
        acc0.x = fmaf(w0.x, nm, acc0.x);
        acc0.y = fmaf(w0.y, nm, acc0.y);
        acc0.z = fmaf(w0.z, nm, acc0.z);
        acc0.w = fmaf(w0.w, nm, acc0.w);
        acc1.x = fmaf(w1.x, nm, acc1.x);
        acc1.y = fmaf(w1.y, nm, acc1.y);
        acc1.z = fmaf(w1.z, nm, acc1.z);
        acc1.w = fmaf(w1.w, nm, acc1.w);
    }
    float4* a4 = (float4*)g_agg;
    a4[(size_t)i * 64 + lane] = acc0;
    a4[(size_t)i * 64 + 32 + lane] = acc1;
}

// ---------------- BatchNorm (deterministic two-stage stats) ----------------
__global__ void k_stats_partial() {
    int j = threadIdx.x;  // 0..255
    float s = 0.f, s2 = 0.f;
    for (int r = blockIdx.x; r < Nn; r += gridDim.x) {
        float v = g_agg[(size_t)r * Hh + j];
        s += v;
        s2 += v * v;
    }
    g_part[blockIdx.x * 2 * Hh + j] = s;
    g_part[blockIdx.x * 2 * Hh + Hh + j] = s2;
}

__global__ void k_stats_reduce() {
    int j = blockIdx.x * blockDim.x + threadIdx.x;  // 0..511
    if (j >= 2 * Hh) return;
    float s = 0.f;
    for (int b = 0; b < STATS_BLOCKS; b++) s += g_part[b * 2 * Hh + j];
    g_stats[j] = s;
}

__global__ void k_bn_relu(const float* __restrict__ gamma,
                          const float* __restrict__ beta) {
    int idx = blockIdx.x * blockDim.x + threadIdx.x;
    const int total = Nn * 64;
    if (idx >= total) return;
    int c4 = (idx & 63) * 4;
    const float4* a4 = (const float4*)g_agg;
    float4 v = a4[idx];
    float out[4];
    float in[4] = {v.x, v.y, v.z, v.w};
    const float invN = 1.0f / (float)Nn;
#pragma unroll
    for (int q = 0; q < 4; q++) {
        int j = c4 + q;
        float mu = g_stats[j] * invN;
        float var = fmaxf(g_stats[Hh + j] * invN - mu * mu, 0.0f);
        float y = (in[q] - mu) * rsqrtf(var + EPSV) * gamma[j] + beta[j];
        out[q] = fmaxf(y, 0.0f);
    }
    ((float4*)g_h)[idx] = make_float4(out[0], out[1], out[2], out[3]);
}

// ---------------- final layers ----------------
__global__ void k_gather(const int* __restrict__ train) {
    int idx = blockIdx.x * blockDim.x + threadIdx.x;
    const int total = Tt * 64;
    if (idx >= total) return;
    int t = idx >> 6;
    int c = idx & 63;
    int node = train[t];
    ((float4*)g_gath)[idx] = ((const float4*)g_h)[(size_t)node * 64 + c];
}

__global__ void k_out(const float* __restrict__ bl,
                      const float* __restrict__ Wf,
                      const float* __restrict__ bf,
                      float* __restrict__ out) {
    int warp = (blockIdx.x * blockDim.x + threadIdx.x) >> 5;
    int lane = threadIdx.x & 31;
    if (warp >= Tt) return;
    float acc = 0.f;
    const float* hp = g_hw + (size_t)warp * Hh;
#pragma unroll
    for (int j0 = 0; j0 < Hh; j0 += 32) {
        int j = j0 + lane;
        float v = fmaxf(hp[j] + bl[j], 0.0f);
        acc = fmaf(v, Wf[j], acc);
    }
#pragma unroll
    for (int o = 16; o > 0; o >>= 1) acc += __shfl_xor_sync(0xffffffffu, acc, o);
    if (lane == 0) out[warp] = acc + bf[0];
}

// ---------------- launch ----------------
extern "C" void kernel_launch(void* const* d_in, const int* in_sizes, int n_in,
                              void* d_out, int out_size) {
    const float* x = (const float*)d_in[0];
    const int* ei = (const int*)d_in[1];     // int32 (JAX x64 disabled)
    const int* train = (const int*)d_in[2];  // int32
    const float* W1 = (const float*)d_in[3];
    const float* W2 = (const float*)d_in[5];
    const float* W3 = (const float*)d_in[7];
    const float* g1 = (const float*)d_in[9];
    const float* be1 = (const float*)d_in[10];
    const float* g2 = (const float*)d_in[11];
    const float* be2 = (const float*)d_in[12];
    const float* g3 = (const float*)d_in[13];
    const float* be3 = (const float*)d_in[14];
    const float* Wl = (const float*)d_in[15];
    const float* bl = (const float*)d_in[16];
    const float* Wf = (const float*)d_in[17];
    const float* bf = (const float*)d_in[18];
    float* out = (float*)d_out;

    const int* row = ei;
    const int* col = ei + Ee;

    float* p_hw = nullptr;
    float* p_h = nullptr;
    float* p_gath = nullptr;
    cudaGetSymbolAddress((void**)&p_hw, g_hw);
    cudaGetSymbolAddress((void**)&p_h, g_h);
    cudaGetSymbolAddress((void**)&p_gath, g_gath);

    // ---- graph preprocessing ----
    k_zero_cnt<<<(Nn + 255) / 256, 256>>>();
    k_count<<<(Ee + 255) / 256, 256>>>(row);
    k_disqrt<<<(Nn + 255) / 256, 256>>>();
    k_scan<<<1, 1024>>>();
    k_scatter<<<(Ee + 255) / 256, 256>>>(row, col);

    dim3 gemm_grid(2, (Nn + 127) / 128);
    const int agg_blocks = (Nn * 32 + 255) / 256;
    const int bn_blocks = (Nn * 64 + 255) / 256;

    // ---- layer 1 ----
    k_sgemm<<<gemm_grid, 256>>>(x, W1, p_hw, Nn, Dd);
    k_agg<<<agg_blocks, 256>>>();
    k_stats_partial<<<STATS_BLOCKS, 256>>>();
    k_stats_reduce<<<1, 512>>>();
    k_bn_relu<<<bn_blocks, 256>>>(g1, be1);

    // ---- layer 2 ----
    k_sgemm<<<gemm_grid, 256>>>(p_h, W2, p_hw, Nn, Hh);
    k_agg<<<agg_blocks, 256>>>();
    k_stats_partial<<<STATS_BLOCKS, 256>>>();
    k_stats_reduce<<<1, 512>>>();
    k_bn_relu<<<bn_blocks, 256>>>(g2, be2);

    // ---- layer 3 ----
    k_sgemm<<<gemm_grid, 256>>>(p_h, W3, p_hw, Nn, Hh);
    k_agg<<<agg_blocks, 256>>>();
    k_stats_partial<<<STATS_BLOCKS, 256>>>();
    k_stats_reduce<<<1, 512>>>();
    k_bn_relu<<<bn_blocks, 256>>>(g3, be3);

    // ---- head: gather train rows, Wl GEMM, fused relu + Wf dot ----
    k_gather<<<(Tt * 64 + 255) / 256, 256>>>(train);
    dim3 head_grid(2, (Tt + 127) / 128);
    k_sgemm<<<head_grid, 256>>>(p_gath, Wl, p_hw, Tt, Hh);
    k_out<<<(Tt * 32 + 255) / 256, 256>>>(bl, Wf, bf, out);
}